// round 2
// baseline (speedup 1.0000x reference)
#include <cuda_runtime.h>
#include <cstdint>
#include <cstddef>

#define B_   8
#define T_   2048
#define D_   1024
#define H_   4
#define HS_  256
#define U_   1365
#define U2_  2730
#define UP_  1376
#define BT_  (B_ * T_)
#define EPSV 1e-5f

// ---------- scratch (static __device__ arrays; no allocation) ----------
__device__ float g_xn[(size_t)BT_ * D_];
__device__ float g_ifin[(size_t)BT_ * D_];
__device__ float g_iflin[(size_t)BT_ * 2048];
__device__ float g_zolin[(size_t)BT_ * 2048];
__device__ float g_zn[(size_t)BT_ * D_];
__device__ float g_up[(size_t)BT_ * U2_];
__device__ float g_act[(size_t)BT_ * UP_];
__device__ float g_whhT[H_ * HS_ * 1024];
__device__ float g_downw[(size_t)D_ * UP_];

// ---------- LayerNorm over D per (b,t) ----------
__global__ void __launch_bounds__(256) ln_kernel(const float* __restrict__ x,
                                                 const float* __restrict__ ln_w,
                                                 const float* __restrict__ ln_b) {
    __shared__ float sred[18];
    const int bt = blockIdx.x, tid = threadIdx.x;
    const float4 xv = reinterpret_cast<const float4*>(x + (size_t)bt * D_)[tid];
    float s = xv.x + xv.y + xv.z + xv.w;
    float q = xv.x * xv.x + xv.y * xv.y + xv.z * xv.z + xv.w * xv.w;
#pragma unroll
    for (int off = 16; off; off >>= 1) {
        s += __shfl_xor_sync(0xffffffffu, s, off);
        q += __shfl_xor_sync(0xffffffffu, q, off);
    }
    if ((tid & 31) == 0) { sred[tid >> 5] = s; sred[8 + (tid >> 5)] = q; }
    __syncthreads();
    if (tid == 0) {
        float ts = 0.f, tq = 0.f;
#pragma unroll
        for (int i = 0; i < 8; i++) { ts += sred[i]; tq += sred[8 + i]; }
        sred[16] = ts; sred[17] = tq;
    }
    __syncthreads();
    const float mean = sred[16] * (1.f / D_);
    const float var  = sred[17] * (1.f / D_) - mean * mean;
    const float inv  = rsqrtf(var + EPSV);
    const float4 wv = reinterpret_cast<const float4*>(ln_w)[tid];
    const float4 bv = reinterpret_cast<const float4*>(ln_b)[tid];
    float4 r;
    r.x = (xv.x - mean) * inv * wv.x + bv.x;
    r.y = (xv.y - mean) * inv * wv.y + bv.y;
    r.z = (xv.z - mean) * inv * wv.z + bv.z;
    r.w = (xv.w - mean) * inv * wv.w + bv.w;
    reinterpret_cast<float4*>(g_xn + (size_t)bt * D_)[tid] = r;
}

// ---------- causal depthwise conv (K=4) + swish ----------
__global__ void __launch_bounds__(256) conv_swish_kernel(const float* __restrict__ conv_w,
                                                         const float* __restrict__ conv_b) {
    const int bt = blockIdx.x;
    const int b = bt / T_, t = bt % T_;
    const int tid = threadIdx.x, c0 = tid * 4;
    float4 acc = reinterpret_cast<const float4*>(conv_b)[tid];
    const float4 w0 = reinterpret_cast<const float4*>(conv_w)[c0 + 0];
    const float4 w1 = reinterpret_cast<const float4*>(conv_w)[c0 + 1];
    const float4 w2 = reinterpret_cast<const float4*>(conv_w)[c0 + 2];
    const float4 w3 = reinterpret_cast<const float4*>(conv_w)[c0 + 3];
#pragma unroll
    for (int k = 0; k < 4; k++) {
        const int tt = t - 3 + k;
        if (tt >= 0) {
            const float4 xv =
                reinterpret_cast<const float4*>(g_xn + (size_t)(b * T_ + tt) * D_)[tid];
            acc.x += ((const float*)&w0)[k] * xv.x;
            acc.y += ((const float*)&w1)[k] * xv.y;
            acc.z += ((const float*)&w2)[k] * xv.z;
            acc.w += ((const float*)&w3)[k] * xv.w;
        }
    }
    float4 o;
    o.x = acc.x / (1.f + expf(-acc.x));
    o.y = acc.y / (1.f + expf(-acc.y));
    o.z = acc.z / (1.f + expf(-acc.z));
    o.w = acc.w / (1.f + expf(-acc.w));
    reinterpret_cast<float4*>(g_ifin + (size_t)bt * D_)[tid] = o;
}

// ---------- weight_hh [H][1024][256] -> [H][256][1024] ----------
__global__ void transpose_whh(const float* __restrict__ whh) {
    __shared__ float tile[32][33];
    const int h = blockIdx.z;
    const int o0 = blockIdx.x * 32, s0 = blockIdx.y * 32;
    const int tx = threadIdx.x, ty = threadIdx.y;
    for (int i = ty; i < 32; i += 8)
        tile[i][tx] = whh[((size_t)h * 1024 + o0 + i) * 256 + s0 + tx];
    __syncthreads();
    for (int i = ty; i < 32; i += 8)
        g_whhT[((size_t)h * 256 + s0 + i) * 1024 + o0 + tx] = tile[tx][i];
}

// ---------- pad down_w rows 1365 -> 1376 ----------
__global__ void pad_downw_kernel(const float* __restrict__ dw) {
    const int n = blockIdx.x;
    const int j = blockIdx.y * 256 + threadIdx.x;
    if (j < UP_)
        g_downw[(size_t)n * UP_ + j] = (j < U_) ? dw[(size_t)n * U_ + j] : 0.f;
}

// ---------- fp32 GEMM: C[m][n] = sum_k A[m][k]*Bw[n][k] (+bias)(+res) ----------
__global__ void __launch_bounds__(256) gemm_nt(const float* __restrict__ A, int lda,
                                               const float* __restrict__ Bw, int ldb,
                                               float* __restrict__ C, int ldc,
                                               int N, int K,
                                               const float* __restrict__ bias,
                                               const float* __restrict__ res) {
    __shared__ float As[16][132];
    __shared__ float Bs[16][132];
    const int m0 = blockIdx.y * 128, n0 = blockIdx.x * 128;
    const int tid = threadIdx.x;
    const int tx = tid & 15, ty = tid >> 4;
    const int lr = tid >> 1, lk = (tid & 1) * 8;
    float acc[8][8];
#pragma unroll
    for (int i = 0; i < 8; i++)
#pragma unroll
        for (int j = 0; j < 8; j++) acc[i][j] = 0.f;

    for (int k0 = 0; k0 < K; k0 += 16) {
        {
            const int gm = m0 + lr;
            const float4 a0 = *reinterpret_cast<const float4*>(A + (size_t)gm * lda + k0 + lk);
            const float4 a1 = *reinterpret_cast<const float4*>(A + (size_t)gm * lda + k0 + lk + 4);
            As[lk + 0][lr] = a0.x; As[lk + 1][lr] = a0.y;
            As[lk + 2][lr] = a0.z; As[lk + 3][lr] = a0.w;
            As[lk + 4][lr] = a1.x; As[lk + 5][lr] = a1.y;
            As[lk + 6][lr] = a1.z; As[lk + 7][lr] = a1.w;
        }
        {
            const int gn = n0 + lr;
            float v[8];
            if (gn < N) {
                const float4 b0 = *reinterpret_cast<const float4*>(Bw + (size_t)gn * ldb + k0 + lk);
                const float4 b1 = *reinterpret_cast<const float4*>(Bw + (size_t)gn * ldb + k0 + lk + 4);
                v[0] = b0.x; v[1] = b0.y; v[2] = b0.z; v[3] = b0.w;
                v[4] = b1.x; v[5] = b1.y; v[6] = b1.z; v[7] = b1.w;
            } else {
#pragma unroll
                for (int j = 0; j < 8; j++) v[j] = 0.f;
            }
#pragma unroll
            for (int j = 0; j < 8; j++) Bs[lk + j][lr] = v[j];
        }
        __syncthreads();
#pragma unroll
        for (int kk = 0; kk < 16; kk++) {
            float a[8], bb[8];
            const float4 a0 = *reinterpret_cast<const float4*>(&As[kk][ty * 8]);
            const float4 a1 = *reinterpret_cast<const float4*>(&As[kk][ty * 8 + 4]);
            a[0] = a0.x; a[1] = a0.y; a[2] = a0.z; a[3] = a0.w;
            a[4] = a1.x; a[5] = a1.y; a[6] = a1.z; a[7] = a1.w;
            const float4 b0 = *reinterpret_cast<const float4*>(&Bs[kk][tx * 8]);
            const float4 b1 = *reinterpret_cast<const float4*>(&Bs[kk][tx * 8 + 4]);
            bb[0] = b0.x; bb[1] = b0.y; bb[2] = b0.z; bb[3] = b0.w;
            bb[4] = b1.x; bb[5] = b1.y; bb[6] = b1.z; bb[7] = b1.w;
#pragma unroll
            for (int i = 0; i < 8; i++)
#pragma unroll
                for (int j = 0; j < 8; j++) acc[i][j] += a[i] * bb[j];
        }
        __syncthreads();
    }
#pragma unroll
    for (int i = 0; i < 8; i++) {
        const int gm = m0 + ty * 8 + i;
#pragma unroll
        for (int j = 0; j < 8; j++) {
            const int gn = n0 + tx * 8 + j;
            if (gn < N) {
                float vv = acc[i][j];
                if (bias) vv += bias[gn];
                if (res)  vv += res[(size_t)gm * ldc + gn];
                C[(size_t)gm * ldc + gn] = vv;
            }
        }
    }
}

// ---------- recurrence: one CTA per (b,h), 2048 sequential steps ----------
__global__ void __launch_bounds__(256) recurrence_kernel(const float* __restrict__ bias,
                                                         const float* __restrict__ gn_w,
                                                         const float* __restrict__ gn_b) {
    const int bh = blockIdx.x;
    const int b = bh >> 2, h = bh & 3;
    const int tid = threadIdx.x;
    __shared__ float sh_h[HS_];
    __shared__ float sh_pre[1024];
    __shared__ float sred[18];

    sh_h[tid] = 0.f;
    float c_s = 0.f, n_s = 0.f, m_s = 0.f;
    const int o4 = tid * 4;
    const float4 bq = *reinterpret_cast<const float4*>(&bias[h * 1024 + o4]);
    const float* Wt = g_whhT + (size_t)h * HS_ * 1024;
    const float* linp; int lcol;
    if (o4 < 512) { linp = g_iflin; lcol = h * 512 + o4; }
    else          { linp = g_zolin; lcol = h * 512 + o4 - 512; }
    const float gw = gn_w[h * HS_ + tid];
    const float gb = gn_b[h * HS_ + tid];
    __syncthreads();

    for (int t = 0; t < T_; t++) {
        float ax = 0.f, ay = 0.f, az = 0.f, aw = 0.f;
#pragma unroll 8
        for (int s = 0; s < HS_; s++) {
            const float hs = sh_h[s];
            const float4 w = *reinterpret_cast<const float4*>(&Wt[(size_t)s * 1024 + o4]);
            ax += hs * w.x; ay += hs * w.y; az += hs * w.z; aw += hs * w.w;
        }
        const float4 lp = *reinterpret_cast<const float4*>(
            &linp[(size_t)(b * T_ + t) * 2048 + lcol]);
        sh_pre[o4 + 0] = ax + lp.x + bq.x;
        sh_pre[o4 + 1] = ay + lp.y + bq.y;
        sh_pre[o4 + 2] = az + lp.z + bq.z;
        sh_pre[o4 + 3] = aw + lp.w + bq.w;
        __syncthreads();

        const float iv = sh_pre[tid];
        const float fv = sh_pre[256 + tid];
        const float zv = tanhf(sh_pre[512 + tid]);
        const float og = 1.f / (1.f + expf(-sh_pre[768 + tid]));
        const float mn = fmaxf(fv + m_s, iv);
        const float ie = expf(iv - mn);
        const float fe = expf(fv + m_s - mn);
        c_s = fe * c_s + ie * zv;
        n_s = fe * n_s + ie;
        m_s = mn;
        const float hv = og * (c_s / n_s);

        float s1 = hv, s2 = hv * hv;
#pragma unroll
        for (int off = 16; off; off >>= 1) {
            s1 += __shfl_xor_sync(0xffffffffu, s1, off);
            s2 += __shfl_xor_sync(0xffffffffu, s2, off);
        }
        if ((tid & 31) == 0) { sred[tid >> 5] = s1; sred[8 + (tid >> 5)] = s2; }
        __syncthreads();
        if (tid == 0) {
            float a = 0.f, bb = 0.f;
#pragma unroll
            for (int i = 0; i < 8; i++) { a += sred[i]; bb += sred[8 + i]; }
            sred[16] = a; sred[17] = bb;
        }
        __syncthreads();
        const float mu  = sred[16] * (1.f / HS_);
        const float var = sred[17] * (1.f / HS_) - mu * mu;
        const float inv = rsqrtf(var + EPSV);
        g_zn[(size_t)(b * T_ + t) * D_ + h * HS_ + tid] = (hv - mu) * inv * gw + gb;
        sh_h[tid] = hv;
        __syncthreads();
    }
}

// ---------- GLU: act = gelu_tanh(u1) * u2, padded to UP_ ----------
__global__ void __launch_bounds__(256) glu_kernel() {
    const int bt = blockIdx.x;
    const float* up = g_up + (size_t)bt * U2_;
    float* act = g_act + (size_t)bt * UP_;
    for (int j = threadIdx.x; j < UP_; j += 256) {
        float v = 0.f;
        if (j < U_) {
            const float u1 = up[j], u2 = up[U_ + j];
            const float g =
                0.5f * u1 * (1.f + tanhf(0.7978845608028654f * (u1 + 0.044715f * u1 * u1 * u1)));
            v = g * u2;
        }
        act[j] = v;
    }
}

extern "C" void kernel_launch(void* const* d_in, const int* in_sizes, int n_in,
                              void* d_out, int out_size) {
    const float* x       = (const float*)d_in[0];
    const float* ln_w    = (const float*)d_in[1];
    const float* ln_b    = (const float*)d_in[2];
    const float* conv_w  = (const float*)d_in[3];
    const float* conv_b  = (const float*)d_in[4];
    const float* w_if    = (const float*)d_in[5];
    const float* w_zo    = (const float*)d_in[6];
    const float* w_hh    = (const float*)d_in[7];
    const float* bias    = (const float*)d_in[8];
    const float* gn_w    = (const float*)d_in[9];
    const float* gn_b    = (const float*)d_in[10];
    const float* up_w    = (const float*)d_in[11];
    const float* up_b    = (const float*)d_in[12];
    const float* down_w  = (const float*)d_in[13];
    const float* down_b  = (const float*)d_in[14];
    float* out = (float*)d_out;

    float *p_xn, *p_ifin, *p_iflin, *p_zolin, *p_zn, *p_up, *p_act, *p_dw;
    cudaGetSymbolAddress((void**)&p_xn, g_xn);
    cudaGetSymbolAddress((void**)&p_ifin, g_ifin);
    cudaGetSymbolAddress((void**)&p_iflin, g_iflin);
    cudaGetSymbolAddress((void**)&p_zolin, g_zolin);
    cudaGetSymbolAddress((void**)&p_zn, g_zn);
    cudaGetSymbolAddress((void**)&p_up, g_up);
    cudaGetSymbolAddress((void**)&p_act, g_act);
    cudaGetSymbolAddress((void**)&p_dw, g_downw);

    ln_kernel<<<BT_, 256>>>(x, ln_w, ln_b);
    conv_swish_kernel<<<BT_, 256>>>(conv_w, conv_b);
    transpose_whh<<<dim3(32, 8, 4), dim3(32, 8)>>>(w_hh);
    pad_downw_kernel<<<dim3(1024, 6), 256>>>(down_w);
    gemm_nt<<<dim3(16, 128), 256>>>(p_ifin, 1024, w_if, 1024, p_iflin, 2048,
                                    2048, 1024, nullptr, nullptr);
    gemm_nt<<<dim3(16, 128), 256>>>(p_xn, 1024, w_zo, 1024, p_zolin, 2048,
                                    2048, 1024, nullptr, nullptr);
    recurrence_kernel<<<32, 256>>>(bias, gn_w, gn_b);
    gemm_nt<<<dim3(22, 128), 256>>>(p_zn, 1024, up_w, 1024, p_up, U2_,
                                    U2_, 1024, up_b, nullptr);
    glu_kernel<<<BT_, 256>>>();
    gemm_nt<<<dim3(8, 128), 256>>>(p_act, UP_, p_dw, UP_, out, 1024,
                                   1024, UP_, down_b, x);
}